// round 11
// baseline (speedup 1.0000x reference)
#include <cuda_runtime.h>
#include <cuda_pipeline.h>

// Fused filtfilt (order-2 IIR) over 1024 rows x 32768 fp32 samples.
//
// - Reference's max-abs normalization cancels exactly (linear, zero state).
// - Poles |lambda|=0.577 -> 24-step warm-up => ~1.9e-6 state error (tol 1e-3).
// - State-space unroll-by-4: s_{t+4} = A^4 s_t + sum_j A^{3-j} g x_{t+j}.
// - Persistent warps, cp.async double-buffered segments, unrolled fast path.
// - R10: SEG 1408->1280 (CL=40) => smem 42.5KB/block and launch_bounds(128,5)
//   => 5 blocks/SM = 20 warps (was 16). Dead segments guarded out.

#define N        32768
#define PAD      9
#define NE       (N + 2 * PAD)        // 32786
#define ROWS     1024
#define WARM     24
#define CL       40
#define SEG      (CL * 32)            // 1280
#define NSEG     28                   // 28*1280 = 35840 (segs 26,27 dead)
#define WARPS    4
#define THREADS  (WARPS * 32)
#define SPW      (NSEG / WARPS)       // 7
#define WWIN     (SEG + 48)           // 1328 floats per buffer
#define MOFF     (WARM - 1)           // 23
#define GPL      (CL / 4)             // 10 body groups per lane

struct C {
    float b0, na1, na2;
    float g3x, g3y, g2x, g2y, g1x, g1y, g0x, g0y;
    float p2x, p2y, p3x, p3y;
    float m00, m01, m10, m11;
};

__device__ __forceinline__ C make_coef(const float* __restrict__ b,
                                       const float* __restrict__ a) {
    C c;
    float ia0 = 1.0f / a[0];
    float b0 = b[0] * ia0, b1 = b[1] * ia0, b2 = b[2] * ia0;
    float na1 = -(a[1] * ia0), na2 = -(a[2] * ia0);
    float g0 = fmaf(na1, b0, b1);
    float g1 = fmaf(na2, b0, b2);
    float A2_00 = fmaf(na1, na1, na2), A2_01 = na1;
    float A2_10 = na2 * na1,           A2_11 = na2;
    float A3_00 = fmaf(A2_00, na1, A2_01 * na2), A3_01 = A2_00;
    float A3_10 = fmaf(A2_10, na1, A2_11 * na2), A3_11 = A2_10;
    c.m00 = fmaf(A3_00, na1, A3_01 * na2); c.m01 = A3_00;
    c.m10 = fmaf(A3_10, na1, A3_11 * na2); c.m11 = A3_10;
    c.g3x = g0;                          c.g3y = g1;
    c.g2x = fmaf(na1, g0, g1);           c.g2y = na2 * g0;
    c.g1x = fmaf(A2_00, g0, A2_01 * g1); c.g1y = fmaf(A2_10, g0, A2_11 * g1);
    c.g0x = fmaf(A3_00, g0, A3_01 * g1); c.g0y = fmaf(A3_10, g0, A3_11 * g1);
    c.p2x = A2_00; c.p2y = A2_01;
    c.p3x = A3_00; c.p3y = A3_01;
    c.b0 = b0; c.na1 = na1; c.na2 = na2;
    return c;
}

__device__ __forceinline__ void warm4(const C& c, float x0, float x1,
                                      float x2, float x3,
                                      float& z0, float& z1) {
    float w0 = fmaf(c.g0x, x0, fmaf(c.g1x, x1, fmaf(c.g2x, x2, c.g3x * x3)));
    float w1 = fmaf(c.g0y, x0, fmaf(c.g1y, x1, fmaf(c.g2y, x2, c.g3y * x3)));
    float nz0 = fmaf(c.m00, z0, fmaf(c.m01, z1, w0));
    float nz1 = fmaf(c.m10, z0, fmaf(c.m11, z1, w1));
    z0 = nz0; z1 = nz1;
}

__device__ __forceinline__ void warm1(const C& c, float xv,
                                      float& z0, float& z1) {
    float nz0 = fmaf(c.na1, z0, fmaf(c.g3x, xv, z1));
    float nz1 = fmaf(c.na2, z0, c.g3y * xv);
    z0 = nz0; z1 = nz1;
}

__device__ __forceinline__ void step4(const C& c, float x0, float x1,
                                      float x2, float x3,
                                      float& z0, float& z1,
                                      float& y0, float& y1,
                                      float& y2, float& y3) {
    y0 = fmaf(c.b0, x0, z0);
    y1 = fmaf(c.b0, x1, fmaf(c.g3x, x0, fmaf(c.na1, z0, z1)));
    y2 = fmaf(c.b0, x2, fmaf(c.g3x, x1,
             fmaf(c.g2x, x0, fmaf(c.p2x, z0, c.p2y * z1))));
    y3 = fmaf(c.b0, x3, fmaf(c.g3x, x2, fmaf(c.g2x, x1,
             fmaf(c.g1x, x0, fmaf(c.p3x, z0, c.p3y * z1)))));
    warm4(c, x0, x1, x2, x3, z0, z1);
}

__device__ __forceinline__ void step1(const C& c, float xv,
                                      float& z0, float& z1, float& y) {
    y = fmaf(c.b0, xv, z0);
    warm1(c, xv, z0, z1);
}

// Synchronous fill with odd-extension mirrors — edge segments only.
__device__ __forceinline__ void fill_direct(float* ws, const float* __restrict__ xr,
                                            int off0, int lane) {
    #pragma unroll 4
    for (int idx = lane; idx < WWIN; idx += 32) {
        int i = off0 + idx;
        float v;
        if (i < 0)       v = 2.0f * xr[0]     - xr[-i];
        else if (i >= N) v = 2.0f * xr[N - 1] - xr[2 * N - 2 - i];
        else             v = xr[i];
        ws[idx] = v;
    }
}

// Fully-unrolled compute for interior segments. Lane l:
//   warm groups  ws4[GPL*l + 0 .. 5]   (m in [40l, 40l+24))
//   body groups  ws4[GPL*l + 6 .. 15]  (t in [40l+1, 40l+41))
//   lane31 tail  ws4[GPL*31 + 16..21]
__device__ __forceinline__ void compute_fast(float* ws, int lane, const C& c,
                                             float* __restrict__ outr, int off0) {
    float4* ws4 = (float4*)ws;
    const int gb = GPL * lane;

    // forward warm-up
    float z0 = 0.0f, z1 = 0.0f;
    #pragma unroll
    for (int g = 0; g < 5; ++g) {
        float4 f = ws4[gb + g];
        warm4(c, f.x, f.y, f.z, f.w, z0, z1);
    }
    if (lane == 0) {
        warm1(c, ws[20], z0, z1);
        warm1(c, ws[21], z0, z1);
        warm1(c, ws[22], z0, z1);
    } else {
        float4 f = ws4[gb + 5];
        warm4(c, f.x, f.y, f.z, f.w, z0, z1);
    }
    __syncwarp();

    // forward body (in-place x -> y1)
    if (lane == 0) { float y; step1(c, ws[23], z0, z1, y); ws[23] = y; }
    #pragma unroll
    for (int g = 6; g < 6 + GPL; ++g) {
        float4 f = ws4[gb + g];
        float y0, y1, y2, y3;
        step4(c, f.x, f.y, f.z, f.w, z0, z1, y0, y1, y2, y3);
        ws4[gb + g] = make_float4(y0, y1, y2, y3);
    }
    if (lane == 31) {                  // tail feeds backward warm-up
        #pragma unroll
        for (int g = 6 + GPL; g < 12 + GPL; ++g) {
            float4 f = ws4[gb + g];
            float y0, y1, y2, y3;
            step4(c, f.x, f.y, f.z, f.w, z0, z1, y0, y1, y2, y3);
            ws4[gb + g] = make_float4(y0, y1, y2, y3);
        }
    }
    __syncwarp();

    // backward warm-up (time-descending)
    z0 = 0.0f; z1 = 0.0f;
    #pragma unroll
    for (int g = 11 + GPL; g > 5 + GPL; --g) {
        float4 f = ws4[gb + g];
        warm4(c, f.w, f.z, f.y, f.x, z0, z1);
    }
    __syncwarp();

    // backward body (in-place y1 -> y2)
    #pragma unroll
    for (int g = 5 + GPL; g >= 6; --g) {
        float4 f = ws4[gb + g];
        float y0, y1, y2, y3;
        step4(c, f.w, f.z, f.y, f.x, z0, z1, y0, y1, y2, y3);
        ws4[gb + g] = make_float4(y3, y2, y1, y0);
    }
    if (lane == 0) { float y; step1(c, ws[23], z0, z1, y); ws[23] = y; }
    __syncwarp();

    // store
    float4* dst4 = (float4*)(outr + off0);
    if (lane == 0) outr[off0 + 23] = ws[23];
    #pragma unroll
    for (int i = 0; i < GPL; ++i) {
        int mi = 6 + lane + 32 * i;
        dst4[mi] = ws4[mi];
    }
}

// Generic compute for edge/partial segments.
__device__ __forceinline__ void compute_generic(float* ws, int lane, const C& c,
                                                float* __restrict__ outr,
                                                int base, int off0) {
    float4* ws4 = (float4*)ws;
    const int tlen = min(SEG, NE - base);

    const int s    = lane * CL + 1;
    const int sbeg = (lane == 0) ? 0 : s;
    const bool active = (sbeg < tlen);
    const int e = active ? min(s + CL, tlen) : sbeg;

    float z0 = 0.0f, z1 = 0.0f;
    if (active) {
        if (lane == 0) {
            if (base > 0) {
                #pragma unroll
                for (int g = 0; g < 5; ++g) {
                    float4 f = ws4[g];
                    warm4(c, f.x, f.y, f.z, f.w, z0, z1);
                }
                warm1(c, ws[20], z0, z1);
                warm1(c, ws[21], z0, z1);
                warm1(c, ws[22], z0, z1);
            }                            // base==0: exact zero state
        } else {
            const float4* p4 = ws4 + ((s - 1) >> 2);
            #pragma unroll
            for (int g = 0; g < WARM / 4; ++g) {
                float4 f = p4[g];
                warm4(c, f.x, f.y, f.z, f.w, z0, z1);
            }
        }
    }
    __syncwarp();

    if (active) {
        int ebody = e;
        if (e == tlen) ebody = min(e + WARM, NE - base);
        int t = sbeg;
        while (t < ebody && ((t + MOFF) & 3) != 0) {
            float y; step1(c, ws[t + MOFF], z0, z1, y); ws[t + MOFF] = y; ++t;
        }
        for (; t + 4 <= ebody; t += 4) {
            int mi = (t + MOFF) >> 2;
            float4 f = ws4[mi];
            float y0, y1, y2, y3;
            step4(c, f.x, f.y, f.z, f.w, z0, z1, y0, y1, y2, y3);
            ws4[mi] = make_float4(y0, y1, y2, y3);
        }
        for (; t < ebody; ++t) {
            float y; step1(c, ws[t + MOFF], z0, z1, y); ws[t + MOFF] = y;
        }
    }
    __syncwarp();

    z0 = 0.0f; z1 = 0.0f;
    if (active) {
        int u = min(e + WARM - 1, NE - base - 1);
        while (u >= e && ((u + MOFF) & 3) != 3) { warm1(c, ws[u + MOFF], z0, z1); --u; }
        for (; u - 3 >= e; u -= 4) {
            float4 f = ws4[(u + MOFF - 3) >> 2];
            warm4(c, f.w, f.z, f.y, f.x, z0, z1);
        }
        for (; u >= e; --u) warm1(c, ws[u + MOFF], z0, z1);
    }
    __syncwarp();

    if (active) {
        int u = e - 1;
        while (u >= sbeg && ((u + MOFF) & 3) != 3) {
            float y; step1(c, ws[u + MOFF], z0, z1, y); ws[u + MOFF] = y; --u;
        }
        for (; u - 3 >= sbeg; u -= 4) {
            int mi = (u + MOFF - 3) >> 2;
            float4 f = ws4[mi];
            float y0, y1, y2, y3;
            step4(c, f.w, f.z, f.y, f.x, z0, z1, y0, y1, y2, y3);
            ws4[mi] = make_float4(y3, y2, y1, y0);
        }
        for (; u >= sbeg; --u) {
            float y; step1(c, ws[u + MOFF], z0, z1, y); ws[u + MOFF] = y;
        }
    }
    __syncwarp();

    {
        int M0 = max(MOFF, -off0);
        int M1 = min(MOFF + tlen, N - off0);
        int mA = (M0 + 3) & ~3;
        int mB = M1 & ~3;
        if (lane < mA - M0) { int m = M0 + lane; outr[off0 + m] = ws[m]; }
        if (lane < M1 - mB) { int m = mB + lane; outr[off0 + m] = ws[m]; }
        float4* dst4 = (float4*)(outr + off0);
        #pragma unroll 4
        for (int mi = (mA >> 2) + lane; mi < (mB >> 2); mi += 32)
            dst4[mi] = ws4[mi];
    }
}

__global__ __launch_bounds__(THREADS, 5)
void filtfilt_kernel(const float* __restrict__ x,
                     const float* __restrict__ bc,
                     const float* __restrict__ ac,
                     float* __restrict__ out) {
    __shared__ float sm[WARPS * 2 * WWIN];        // 42.5 KB

    const int lane = threadIdx.x & 31;
    const int wid  = threadIdx.x >> 5;
    const int row  = blockIdx.x;

    const float* xr   = x   + (size_t)row * N;
    float*       outr = out + (size_t)row * N;

    const C c = make_coef(bc, ac);

    float* buf0 = sm + wid * (2 * WWIN);
    float* buf1 = buf0 + WWIN;

    // interleaved mapping: iteration q -> segment q*WARPS + wid
    auto seg_of = [&](int q) { return q * WARPS + wid; };
    // fast path: full interior tile with full aligned window and full tail
    auto is_fast = [&](int seg) {
        return seg >= 1 && (seg * SEG - 32 + WWIN) <= N;   // seg <= 24
    };

    auto prefetch = [&](int q, float* buf) {
        const int seg  = seg_of(q);
        const int base = seg * SEG;
        const int off0 = base - 32;
        if (base < NE) {
            if (is_fast(seg)) {
                const float4* __restrict__ src = (const float4*)(xr + off0);
                float4* dst = (float4*)buf;
                #pragma unroll
                for (int i = 0; i < GPL; ++i)
                    __pipeline_memcpy_async(&dst[lane + 32 * i],
                                            &src[lane + 32 * i], 16);
                if (lane < WWIN / 4 - GPL * 32)            // 12 extra groups
                    __pipeline_memcpy_async(&dst[lane + GPL * 32],
                                            &src[lane + GPL * 32], 16);
            } else {
                fill_direct(buf, xr, off0, lane);          // sync, mirrors
            }
        }
        __pipeline_commit();                               // keep group count
    };

    prefetch(0, buf0);
    #pragma unroll
    for (int k = 0; k < SPW; ++k) {
        float* ws = (k & 1) ? buf1 : buf0;
        if (k + 1 < SPW) {
            prefetch(k + 1, (k & 1) ? buf0 : buf1);
            __pipeline_wait_prior(1);                      // group k complete
        } else {
            __pipeline_wait_prior(0);
        }
        __syncwarp();                                      // copies visible

        const int seg  = seg_of(k);
        const int base = seg * SEG;
        const int off0 = base - 32;
        if (base < NE) {
            if (is_fast(seg))
                compute_fast(ws, lane, c, outr, off0);
            else
                compute_generic(ws, lane, c, outr, base, off0);
        }
        __syncwarp();
    }
}

extern "C" void kernel_launch(void* const* d_in, const int* in_sizes, int n_in,
                              void* d_out, int out_size) {
    const float* x = (const float*)d_in[0];
    const float* b = (const float*)d_in[1];
    const float* a = (const float*)d_in[2];
    float* out = (float*)d_out;

    filtfilt_kernel<<<ROWS, THREADS>>>(x, b, a, out);
}

// round 12
// speedup vs baseline: 1.0508x; 1.0508x over previous
#include <cuda_runtime.h>
#include <cuda_pipeline.h>

// Fused filtfilt (order-2 IIR) over 1024 rows x 32768 fp32 samples.
//
// - Reference's max-abs normalization cancels exactly (linear, zero state).
// - Poles |lambda|=0.577 -> 24-step warm-up => ~1.9e-6 state error (tol 1e-3).
// - State-space unroll-by-4: s_{t+4} = A^4 s_t + sum_j A^{3-j} g x_{t+j}.
// - Persistent warps, cp.async double-buffered segments, unrolled fast path.
// - R11: CL=36 (stride 4 mod 8 -> LDS.128 bank-conflict-FREE; R10's CL=40
//   was 8-divisible and caused 2-way conflicts). 37.5KB smem -> 5 blocks/SM
//   = 20 warps.

#define N        32768
#define PAD      9
#define NE       (N + 2 * PAD)        // 32786
#define ROWS     1024
#define WARM     24
#define CL       36                   // gcd(36,32)=4 -> conflict-free LDS.128
#define SEG      (CL * 32)            // 1152
#define NSEG     29                   // 29*1152 = 33408 >= NE
#define WARPS    4
#define THREADS  (WARPS * 32)
#define SPW      8                    // ceil(NSEG/WARPS); dead slots guarded
#define WWIN     (SEG + 48)           // 1200 floats per buffer
#define MOFF     (WARM - 1)           // 23
#define GPL      (CL / 4)             // 9 body groups per lane

struct C {
    float b0, na1, na2;
    float g3x, g3y, g2x, g2y, g1x, g1y, g0x, g0y;
    float p2x, p2y, p3x, p3y;
    float m00, m01, m10, m11;
};

__device__ __forceinline__ C make_coef(const float* __restrict__ b,
                                       const float* __restrict__ a) {
    C c;
    float ia0 = 1.0f / a[0];
    float b0 = b[0] * ia0, b1 = b[1] * ia0, b2 = b[2] * ia0;
    float na1 = -(a[1] * ia0), na2 = -(a[2] * ia0);
    float g0 = fmaf(na1, b0, b1);
    float g1 = fmaf(na2, b0, b2);
    float A2_00 = fmaf(na1, na1, na2), A2_01 = na1;
    float A2_10 = na2 * na1,           A2_11 = na2;
    float A3_00 = fmaf(A2_00, na1, A2_01 * na2), A3_01 = A2_00;
    float A3_10 = fmaf(A2_10, na1, A2_11 * na2), A3_11 = A2_10;
    c.m00 = fmaf(A3_00, na1, A3_01 * na2); c.m01 = A3_00;
    c.m10 = fmaf(A3_10, na1, A3_11 * na2); c.m11 = A3_10;
    c.g3x = g0;                          c.g3y = g1;
    c.g2x = fmaf(na1, g0, g1);           c.g2y = na2 * g0;
    c.g1x = fmaf(A2_00, g0, A2_01 * g1); c.g1y = fmaf(A2_10, g0, A2_11 * g1);
    c.g0x = fmaf(A3_00, g0, A3_01 * g1); c.g0y = fmaf(A3_10, g0, A3_11 * g1);
    c.p2x = A2_00; c.p2y = A2_01;
    c.p3x = A3_00; c.p3y = A3_01;
    c.b0 = b0; c.na1 = na1; c.na2 = na2;
    return c;
}

__device__ __forceinline__ void warm4(const C& c, float x0, float x1,
                                      float x2, float x3,
                                      float& z0, float& z1) {
    float w0 = fmaf(c.g0x, x0, fmaf(c.g1x, x1, fmaf(c.g2x, x2, c.g3x * x3)));
    float w1 = fmaf(c.g0y, x0, fmaf(c.g1y, x1, fmaf(c.g2y, x2, c.g3y * x3)));
    float nz0 = fmaf(c.m00, z0, fmaf(c.m01, z1, w0));
    float nz1 = fmaf(c.m10, z0, fmaf(c.m11, z1, w1));
    z0 = nz0; z1 = nz1;
}

__device__ __forceinline__ void warm1(const C& c, float xv,
                                      float& z0, float& z1) {
    float nz0 = fmaf(c.na1, z0, fmaf(c.g3x, xv, z1));
    float nz1 = fmaf(c.na2, z0, c.g3y * xv);
    z0 = nz0; z1 = nz1;
}

__device__ __forceinline__ void step4(const C& c, float x0, float x1,
                                      float x2, float x3,
                                      float& z0, float& z1,
                                      float& y0, float& y1,
                                      float& y2, float& y3) {
    y0 = fmaf(c.b0, x0, z0);
    y1 = fmaf(c.b0, x1, fmaf(c.g3x, x0, fmaf(c.na1, z0, z1)));
    y2 = fmaf(c.b0, x2, fmaf(c.g3x, x1,
             fmaf(c.g2x, x0, fmaf(c.p2x, z0, c.p2y * z1))));
    y3 = fmaf(c.b0, x3, fmaf(c.g3x, x2, fmaf(c.g2x, x1,
             fmaf(c.g1x, x0, fmaf(c.p3x, z0, c.p3y * z1)))));
    warm4(c, x0, x1, x2, x3, z0, z1);
}

__device__ __forceinline__ void step1(const C& c, float xv,
                                      float& z0, float& z1, float& y) {
    y = fmaf(c.b0, xv, z0);
    warm1(c, xv, z0, z1);
}

// Synchronous fill with odd-extension mirrors — edge segments only.
__device__ __forceinline__ void fill_direct(float* ws, const float* __restrict__ xr,
                                            int off0, int lane) {
    #pragma unroll 4
    for (int idx = lane; idx < WWIN; idx += 32) {
        int i = off0 + idx;
        float v;
        if (i < 0)       v = 2.0f * xr[0]     - xr[-i];
        else if (i >= N) v = 2.0f * xr[N - 1] - xr[2 * N - 2 - i];
        else             v = xr[i];
        ws[idx] = v;
    }
}

// Fully-unrolled compute for interior segments. Lane l:
//   warm groups  ws4[GPL*l + 0 .. 5]       (m in [CL*l, CL*l+24))
//   body groups  ws4[GPL*l + 6 .. 5+GPL]   (t in [CL*l+1, CL*l+CL+1))
//   lane31 tail  ws4[GPL*31 + 6+GPL .. 11+GPL]
__device__ __forceinline__ void compute_fast(float* ws, int lane, const C& c,
                                             float* __restrict__ outr, int off0) {
    float4* ws4 = (float4*)ws;
    const int gb = GPL * lane;

    // forward warm-up
    float z0 = 0.0f, z1 = 0.0f;
    #pragma unroll
    for (int g = 0; g < 5; ++g) {
        float4 f = ws4[gb + g];
        warm4(c, f.x, f.y, f.z, f.w, z0, z1);
    }
    if (lane == 0) {
        warm1(c, ws[20], z0, z1);
        warm1(c, ws[21], z0, z1);
        warm1(c, ws[22], z0, z1);
    } else {
        float4 f = ws4[gb + 5];
        warm4(c, f.x, f.y, f.z, f.w, z0, z1);
    }
    __syncwarp();

    // forward body (in-place x -> y1)
    if (lane == 0) { float y; step1(c, ws[23], z0, z1, y); ws[23] = y; }
    #pragma unroll
    for (int g = 6; g < 6 + GPL; ++g) {
        float4 f = ws4[gb + g];
        float y0, y1, y2, y3;
        step4(c, f.x, f.y, f.z, f.w, z0, z1, y0, y1, y2, y3);
        ws4[gb + g] = make_float4(y0, y1, y2, y3);
    }
    if (lane == 31) {                  // tail feeds backward warm-up
        #pragma unroll
        for (int g = 6 + GPL; g < 12 + GPL; ++g) {
            float4 f = ws4[gb + g];
            float y0, y1, y2, y3;
            step4(c, f.x, f.y, f.z, f.w, z0, z1, y0, y1, y2, y3);
            ws4[gb + g] = make_float4(y0, y1, y2, y3);
        }
    }
    __syncwarp();

    // backward warm-up (time-descending)
    z0 = 0.0f; z1 = 0.0f;
    #pragma unroll
    for (int g = 11 + GPL; g > 5 + GPL; --g) {
        float4 f = ws4[gb + g];
        warm4(c, f.w, f.z, f.y, f.x, z0, z1);
    }
    __syncwarp();

    // backward body (in-place y1 -> y2)
    #pragma unroll
    for (int g = 5 + GPL; g >= 6; --g) {
        float4 f = ws4[gb + g];
        float y0, y1, y2, y3;
        step4(c, f.w, f.z, f.y, f.x, z0, z1, y0, y1, y2, y3);
        ws4[gb + g] = make_float4(y3, y2, y1, y0);
    }
    if (lane == 0) { float y; step1(c, ws[23], z0, z1, y); ws[23] = y; }
    __syncwarp();

    // store
    float4* dst4 = (float4*)(outr + off0);
    if (lane == 0) outr[off0 + 23] = ws[23];
    #pragma unroll
    for (int i = 0; i < GPL; ++i) {
        int mi = 6 + lane + 32 * i;
        dst4[mi] = ws4[mi];
    }
}

// Generic compute for edge/partial segments.
__device__ __forceinline__ void compute_generic(float* ws, int lane, const C& c,
                                                float* __restrict__ outr,
                                                int base, int off0) {
    float4* ws4 = (float4*)ws;
    const int tlen = min(SEG, NE - base);

    const int s    = lane * CL + 1;
    const int sbeg = (lane == 0) ? 0 : s;
    const bool active = (sbeg < tlen);
    const int e = active ? min(s + CL, tlen) : sbeg;

    float z0 = 0.0f, z1 = 0.0f;
    if (active) {
        if (lane == 0) {
            if (base > 0) {
                #pragma unroll
                for (int g = 0; g < 5; ++g) {
                    float4 f = ws4[g];
                    warm4(c, f.x, f.y, f.z, f.w, z0, z1);
                }
                warm1(c, ws[20], z0, z1);
                warm1(c, ws[21], z0, z1);
                warm1(c, ws[22], z0, z1);
            }                            // base==0: exact zero state
        } else {
            const float4* p4 = ws4 + ((s - 1) >> 2);
            #pragma unroll
            for (int g = 0; g < WARM / 4; ++g) {
                float4 f = p4[g];
                warm4(c, f.x, f.y, f.z, f.w, z0, z1);
            }
        }
    }
    __syncwarp();

    if (active) {
        int ebody = e;
        if (e == tlen) ebody = min(e + WARM, NE - base);
        int t = sbeg;
        while (t < ebody && ((t + MOFF) & 3) != 0) {
            float y; step1(c, ws[t + MOFF], z0, z1, y); ws[t + MOFF] = y; ++t;
        }
        for (; t + 4 <= ebody; t += 4) {
            int mi = (t + MOFF) >> 2;
            float4 f = ws4[mi];
            float y0, y1, y2, y3;
            step4(c, f.x, f.y, f.z, f.w, z0, z1, y0, y1, y2, y3);
            ws4[mi] = make_float4(y0, y1, y2, y3);
        }
        for (; t < ebody; ++t) {
            float y; step1(c, ws[t + MOFF], z0, z1, y); ws[t + MOFF] = y;
        }
    }
    __syncwarp();

    z0 = 0.0f; z1 = 0.0f;
    if (active) {
        int u = min(e + WARM - 1, NE - base - 1);
        while (u >= e && ((u + MOFF) & 3) != 3) { warm1(c, ws[u + MOFF], z0, z1); --u; }
        for (; u - 3 >= e; u -= 4) {
            float4 f = ws4[(u + MOFF - 3) >> 2];
            warm4(c, f.w, f.z, f.y, f.x, z0, z1);
        }
        for (; u >= e; --u) warm1(c, ws[u + MOFF], z0, z1);
    }
    __syncwarp();

    if (active) {
        int u = e - 1;
        while (u >= sbeg && ((u + MOFF) & 3) != 3) {
            float y; step1(c, ws[u + MOFF], z0, z1, y); ws[u + MOFF] = y; --u;
        }
        for (; u - 3 >= sbeg; u -= 4) {
            int mi = (u + MOFF - 3) >> 2;
            float4 f = ws4[mi];
            float y0, y1, y2, y3;
            step4(c, f.w, f.z, f.y, f.x, z0, z1, y0, y1, y2, y3);
            ws4[mi] = make_float4(y3, y2, y1, y0);
        }
        for (; u >= sbeg; --u) {
            float y; step1(c, ws[u + MOFF], z0, z1, y); ws[u + MOFF] = y;
        }
    }
    __syncwarp();

    {
        int M0 = max(MOFF, -off0);
        int M1 = min(MOFF + tlen, N - off0);
        int mA = (M0 + 3) & ~3;
        int mB = M1 & ~3;
        if (lane < mA - M0) { int m = M0 + lane; outr[off0 + m] = ws[m]; }
        if (lane < M1 - mB) { int m = mB + lane; outr[off0 + m] = ws[m]; }
        float4* dst4 = (float4*)(outr + off0);
        #pragma unroll 4
        for (int mi = (mA >> 2) + lane; mi < (mB >> 2); mi += 32)
            dst4[mi] = ws4[mi];
    }
}

__global__ __launch_bounds__(THREADS, 5)
void filtfilt_kernel(const float* __restrict__ x,
                     const float* __restrict__ bc,
                     const float* __restrict__ ac,
                     float* __restrict__ out) {
    __shared__ float sm[WARPS * 2 * WWIN];        // 37.5 KB

    const int lane = threadIdx.x & 31;
    const int wid  = threadIdx.x >> 5;
    const int row  = blockIdx.x;

    const float* xr   = x   + (size_t)row * N;
    float*       outr = out + (size_t)row * N;

    const C c = make_coef(bc, ac);

    float* buf0 = sm + wid * (2 * WWIN);
    float* buf1 = buf0 + WWIN;

    auto seg_of = [&](int q) { return q * WARPS + wid; };
    // fast path: interior tile whose aligned window+tail fits inside x
    auto is_fast = [&](int seg) {
        return seg >= 1 && (seg * SEG - 32 + WWIN) <= N;   // seg <= 27
    };

    auto prefetch = [&](int q, float* buf) {
        const int seg  = seg_of(q);
        const int base = seg * SEG;
        const int off0 = base - 32;
        if (base < NE) {
            if (is_fast(seg)) {
                const float4* __restrict__ src = (const float4*)(xr + off0);
                float4* dst = (float4*)buf;
                #pragma unroll
                for (int i = 0; i < GPL; ++i)
                    __pipeline_memcpy_async(&dst[lane + 32 * i],
                                            &src[lane + 32 * i], 16);
                if (lane < WWIN / 4 - GPL * 32)            // 12 extra groups
                    __pipeline_memcpy_async(&dst[lane + GPL * 32],
                                            &src[lane + GPL * 32], 16);
            } else {
                fill_direct(buf, xr, off0, lane);          // sync, mirrors
            }
        }
        __pipeline_commit();                               // keep group count
    };

    prefetch(0, buf0);
    #pragma unroll
    for (int k = 0; k < SPW; ++k) {
        float* ws = (k & 1) ? buf1 : buf0;
        if (k + 1 < SPW) {
            prefetch(k + 1, (k & 1) ? buf0 : buf1);
            __pipeline_wait_prior(1);                      // group k complete
        } else {
            __pipeline_wait_prior(0);
        }
        __syncwarp();                                      // copies visible

        const int seg  = seg_of(k);
        const int base = seg * SEG;
        const int off0 = base - 32;
        if (base < NE) {
            if (is_fast(seg))
                compute_fast(ws, lane, c, outr, off0);
            else
                compute_generic(ws, lane, c, outr, base, off0);
        }
        __syncwarp();
    }
}

extern "C" void kernel_launch(void* const* d_in, const int* in_sizes, int n_in,
                              void* d_out, int out_size) {
    const float* x = (const float*)d_in[0];
    const float* b = (const float*)d_in[1];
    const float* a = (const float*)d_in[2];
    float* out = (float*)d_out;

    filtfilt_kernel<<<ROWS, THREADS>>>(x, b, a, out);
}

// round 13
// speedup vs baseline: 1.2782x; 1.2164x over previous
#include <cuda_runtime.h>
#include <cuda_pipeline.h>

// Fused filtfilt (order-2 IIR) over 1024 rows x 32768 fp32 samples.
//
// - Reference's max-abs normalization cancels exactly (linear, zero state).
// - Poles |lambda|=0.577 -> 24-step warm-up => ~1.9e-6 state error (tol 1e-3).
// - State-space unroll-by-4: s_{t+4} = A^4 s_t + sum_j A^{3-j} g x_{t+j}.
// - R12: TWO independent chains per thread. Segment = 64 chunks of CL=36;
//   lane l runs chunks l and l+32 interleaved in the instruction stream.
//   While chain A waits on LDS / its z-chain, chain B issues -> ~2x per-thread
//   issue utilization. Single smem window per warp serves both chains
//   (36.8KB/block static), CL=36 keeps LDS.128 conflict-free (stride 4 mod 8).

#define N        32768
#define PAD      9
#define NE       (N + 2 * PAD)        // 32786
#define ROWS     1024
#define WARM     24
#define CL       36                   // stride 4 mod 8 -> conflict-free
#define NCH      64                   // chunks per segment (2 per lane)
#define SEG      (CL * NCH)           // 2304
#define NSEG     15                   // 14 full + 1 partial (530)
#define WARPS    4
#define THREADS  (WARPS * 32)
#define SPW      4                    // ceil(NSEG/WARPS); dead slot guarded
#define WWIN     (SEG + 48)           // 2352 floats
#define MOFF     (WARM - 1)           // 23
#define GPL      (CL / 4)             // 9 groups per chunk

struct C {
    float b0, na1, na2;
    float g3x, g3y, g2x, g2y, g1x, g1y, g0x, g0y;
    float p2x, p2y, p3x, p3y;
    float m00, m01, m10, m11;
};

__device__ __forceinline__ C make_coef(const float* __restrict__ b,
                                       const float* __restrict__ a) {
    C c;
    float ia0 = 1.0f / a[0];
    float b0 = b[0] * ia0, b1 = b[1] * ia0, b2 = b[2] * ia0;
    float na1 = -(a[1] * ia0), na2 = -(a[2] * ia0);
    float g0 = fmaf(na1, b0, b1);
    float g1 = fmaf(na2, b0, b2);
    float A2_00 = fmaf(na1, na1, na2), A2_01 = na1;
    float A2_10 = na2 * na1,           A2_11 = na2;
    float A3_00 = fmaf(A2_00, na1, A2_01 * na2), A3_01 = A2_00;
    float A3_10 = fmaf(A2_10, na1, A2_11 * na2), A3_11 = A2_10;
    c.m00 = fmaf(A3_00, na1, A3_01 * na2); c.m01 = A3_00;
    c.m10 = fmaf(A3_10, na1, A3_11 * na2); c.m11 = A3_10;
    c.g3x = g0;                          c.g3y = g1;
    c.g2x = fmaf(na1, g0, g1);           c.g2y = na2 * g0;
    c.g1x = fmaf(A2_00, g0, A2_01 * g1); c.g1y = fmaf(A2_10, g0, A2_11 * g1);
    c.g0x = fmaf(A3_00, g0, A3_01 * g1); c.g0y = fmaf(A3_10, g0, A3_11 * g1);
    c.p2x = A2_00; c.p2y = A2_01;
    c.p3x = A3_00; c.p3y = A3_01;
    c.b0 = b0; c.na1 = na1; c.na2 = na2;
    return c;
}

__device__ __forceinline__ void warm4(const C& c, float x0, float x1,
                                      float x2, float x3,
                                      float& z0, float& z1) {
    float w0 = fmaf(c.g0x, x0, fmaf(c.g1x, x1, fmaf(c.g2x, x2, c.g3x * x3)));
    float w1 = fmaf(c.g0y, x0, fmaf(c.g1y, x1, fmaf(c.g2y, x2, c.g3y * x3)));
    float nz0 = fmaf(c.m00, z0, fmaf(c.m01, z1, w0));
    float nz1 = fmaf(c.m10, z0, fmaf(c.m11, z1, w1));
    z0 = nz0; z1 = nz1;
}

__device__ __forceinline__ void warm1(const C& c, float xv,
                                      float& z0, float& z1) {
    float nz0 = fmaf(c.na1, z0, fmaf(c.g3x, xv, z1));
    float nz1 = fmaf(c.na2, z0, c.g3y * xv);
    z0 = nz0; z1 = nz1;
}

__device__ __forceinline__ void step4(const C& c, float x0, float x1,
                                      float x2, float x3,
                                      float& z0, float& z1,
                                      float& y0, float& y1,
                                      float& y2, float& y3) {
    y0 = fmaf(c.b0, x0, z0);
    y1 = fmaf(c.b0, x1, fmaf(c.g3x, x0, fmaf(c.na1, z0, z1)));
    y2 = fmaf(c.b0, x2, fmaf(c.g3x, x1,
             fmaf(c.g2x, x0, fmaf(c.p2x, z0, c.p2y * z1))));
    y3 = fmaf(c.b0, x3, fmaf(c.g3x, x2, fmaf(c.g2x, x1,
             fmaf(c.g1x, x0, fmaf(c.p3x, z0, c.p3y * z1)))));
    warm4(c, x0, x1, x2, x3, z0, z1);
}

__device__ __forceinline__ void step1(const C& c, float xv,
                                      float& z0, float& z1, float& y) {
    y = fmaf(c.b0, xv, z0);
    warm1(c, xv, z0, z1);
}

// Synchronous fill with odd-extension mirrors — edge segments only.
__device__ __forceinline__ void fill_direct(float* ws, const float* __restrict__ xr,
                                            int off0, int lane) {
    #pragma unroll 4
    for (int idx = lane; idx < WWIN; idx += 32) {
        int i = off0 + idx;
        float v;
        if (i < 0)       v = 2.0f * xr[0]     - xr[-i];
        else if (i >= N) v = 2.0f * xr[N - 1] - xr[2 * N - 2 - i];
        else             v = xr[i];
        ws[idx] = v;
    }
}

// Fully-unrolled dual-chain compute for interior segments (1..13).
// Chain A = chunk `lane`, chain B = chunk `lane+32`.
// Chunk j: warm groups ws4[9j..9j+5], body groups ws4[9j+6..9j+14].
// Lane31 chain B also computes the 24-sample tail (groups 582..587).
__device__ __forceinline__ void compute_fast(float* ws, int lane, const C& c,
                                             float* __restrict__ outr, int off0) {
    float4* ws4 = (float4*)ws;
    const int gA = GPL * lane;            // 9*lane
    const int gB = gA + GPL * 32;         // 9*lane + 288

    // ---- forward warm-up (both chains interleaved) ----
    float a0 = 0.0f, a1 = 0.0f, b0 = 0.0f, b1 = 0.0f;
    #pragma unroll
    for (int g = 0; g < 5; ++g) {
        float4 fA = ws4[gA + g], fB = ws4[gB + g];
        warm4(c, fA.x, fA.y, fA.z, fA.w, a0, a1);
        warm4(c, fB.x, fB.y, fB.z, fB.w, b0, b1);
    }
    {
        float4 fB = ws4[gB + 5];
        warm4(c, fB.x, fB.y, fB.z, fB.w, b0, b1);
        if (lane == 0) {                  // chunk 0 warm stops before m=23
            warm1(c, ws[20], a0, a1);
            warm1(c, ws[21], a0, a1);
            warm1(c, ws[22], a0, a1);
        } else {
            float4 fA = ws4[gA + 5];
            warm4(c, fA.x, fA.y, fA.z, fA.w, a0, a1);
        }
    }
    __syncwarp();

    // ---- forward body (in-place x -> y1) ----
    if (lane == 0) { float y; step1(c, ws[23], a0, a1, y); ws[23] = y; }
    #pragma unroll
    for (int g = 6; g < 6 + GPL; ++g) {
        float4 fA = ws4[gA + g], fB = ws4[gB + g];
        float y0, y1, y2, y3;
        step4(c, fA.x, fA.y, fA.z, fA.w, a0, a1, y0, y1, y2, y3);
        ws4[gA + g] = make_float4(y0, y1, y2, y3);
        step4(c, fB.x, fB.y, fB.z, fB.w, b0, b1, y0, y1, y2, y3);
        ws4[gB + g] = make_float4(y0, y1, y2, y3);
    }
    if (lane == 31) {                     // tail feeds backward warm-up
        #pragma unroll
        for (int g = 6 + GPL; g < 12 + GPL; ++g) {
            float4 f = ws4[gB + g];
            float y0, y1, y2, y3;
            step4(c, f.x, f.y, f.z, f.w, b0, b1, y0, y1, y2, y3);
            ws4[gB + g] = make_float4(y0, y1, y2, y3);
        }
    }
    __syncwarp();

    // ---- backward warm-up (time-descending, both chains) ----
    a0 = a1 = b0 = b1 = 0.0f;
    #pragma unroll
    for (int g = 11 + GPL; g > 5 + GPL; --g) {   // 20..15
        float4 fA = ws4[gA + g], fB = ws4[gB + g];
        warm4(c, fA.w, fA.z, fA.y, fA.x, a0, a1);
        warm4(c, fB.w, fB.z, fB.y, fB.x, b0, b1);
    }
    __syncwarp();

    // ---- backward body (in-place y1 -> y2) ----
    #pragma unroll
    for (int g = 5 + GPL; g >= 6; --g) {         // 14..6
        float4 fA = ws4[gA + g], fB = ws4[gB + g];
        float y0, y1, y2, y3;
        step4(c, fA.w, fA.z, fA.y, fA.x, a0, a1, y0, y1, y2, y3);
        ws4[gA + g] = make_float4(y3, y2, y1, y0);
        step4(c, fB.w, fB.z, fB.y, fB.x, b0, b1, y0, y1, y2, y3);
        ws4[gB + g] = make_float4(y3, y2, y1, y0);
    }
    if (lane == 0) { float y; step1(c, ws[23], a0, a1, y); ws[23] = y; }
    __syncwarp();

    // ---- store: scalar m=23 + groups 6..581 (576 = 18 per lane) ----
    float4* dst4 = (float4*)(outr + off0);
    if (lane == 0) outr[off0 + 23] = ws[23];
    #pragma unroll
    for (int i = 0; i < 18; ++i) {
        int mi = 6 + lane + 32 * i;
        dst4[mi] = ws4[mi];
    }
}

// Generic compute for edge/partial segments (0, 14): both chunks per lane,
// phase-interleaved so cross-chunk dependencies stay warp-synchronous.
__device__ __forceinline__ void compute_generic(float* ws, int lane, const C& c,
                                                float* __restrict__ outr,
                                                int base, int off0) {
    float4* ws4 = (float4*)ws;
    const int tlen = min(SEG, NE - base);

    float z0s[2], z1s[2];
    int   sb[2], en[2];
    bool  act[2];
    #pragma unroll
    for (int k = 0; k < 2; ++k) {
        int j = lane + 32 * k;
        int s = j * CL + 1;
        sb[k]  = (j == 0) ? 0 : s;
        act[k] = sb[k] < tlen;
        en[k]  = act[k] ? min(s + CL, tlen) : sb[k];
        z0s[k] = 0.0f; z1s[k] = 0.0f;
    }

    // ---- forward warm-up ----
    #pragma unroll
    for (int k = 0; k < 2; ++k) if (act[k]) {
        int j = lane + 32 * k;
        if (j == 0) {
            if (base > 0) {
                #pragma unroll
                for (int g = 0; g < 5; ++g) {
                    float4 f = ws4[g];
                    warm4(c, f.x, f.y, f.z, f.w, z0s[k], z1s[k]);
                }
                warm1(c, ws[20], z0s[k], z1s[k]);
                warm1(c, ws[21], z0s[k], z1s[k]);
                warm1(c, ws[22], z0s[k], z1s[k]);
            }                             // base==0: exact zero state
        } else {
            const float4* p4 = ws4 + GPL * j;
            #pragma unroll
            for (int g = 0; g < WARM / 4; ++g) {
                float4 f = p4[g];
                warm4(c, f.x, f.y, f.z, f.w, z0s[k], z1s[k]);
            }
        }
    }
    __syncwarp();

    // ---- forward body (+WARM tail by whichever chunk ends at tlen) ----
    #pragma unroll
    for (int k = 0; k < 2; ++k) if (act[k]) {
        int ebody = en[k];
        if (en[k] == tlen) ebody = min(en[k] + WARM, NE - base);
        int t = sb[k];
        while (t < ebody && ((t + MOFF) & 3) != 0) {
            float y; step1(c, ws[t + MOFF], z0s[k], z1s[k], y); ws[t + MOFF] = y; ++t;
        }
        for (; t + 4 <= ebody; t += 4) {
            int mi = (t + MOFF) >> 2;
            float4 f = ws4[mi];
            float y0, y1, y2, y3;
            step4(c, f.x, f.y, f.z, f.w, z0s[k], z1s[k], y0, y1, y2, y3);
            ws4[mi] = make_float4(y0, y1, y2, y3);
        }
        for (; t < ebody; ++t) {
            float y; step1(c, ws[t + MOFF], z0s[k], z1s[k], y); ws[t + MOFF] = y;
        }
    }
    __syncwarp();

    // ---- backward warm-up ----
    #pragma unroll
    for (int k = 0; k < 2; ++k) {
        z0s[k] = 0.0f; z1s[k] = 0.0f;
        if (act[k]) {
            int u = min(en[k] + WARM - 1, NE - base - 1);
            while (u >= en[k] && ((u + MOFF) & 3) != 3) {
                warm1(c, ws[u + MOFF], z0s[k], z1s[k]); --u;
            }
            for (; u - 3 >= en[k]; u -= 4) {
                float4 f = ws4[(u + MOFF - 3) >> 2];
                warm4(c, f.w, f.z, f.y, f.x, z0s[k], z1s[k]);
            }
            for (; u >= en[k]; --u) warm1(c, ws[u + MOFF], z0s[k], z1s[k]);
        }
    }
    __syncwarp();

    // ---- backward body ----
    #pragma unroll
    for (int k = 0; k < 2; ++k) if (act[k]) {
        int u = en[k] - 1;
        while (u >= sb[k] && ((u + MOFF) & 3) != 3) {
            float y; step1(c, ws[u + MOFF], z0s[k], z1s[k], y); ws[u + MOFF] = y; --u;
        }
        for (; u - 3 >= sb[k]; u -= 4) {
            int mi = (u + MOFF - 3) >> 2;
            float4 f = ws4[mi];
            float y0, y1, y2, y3;
            step4(c, f.w, f.z, f.y, f.x, z0s[k], z1s[k], y0, y1, y2, y3);
            ws4[mi] = make_float4(y3, y2, y1, y0);
        }
        for (; u >= sb[k]; --u) {
            float y; step1(c, ws[u + MOFF], z0s[k], z1s[k], y); ws[u + MOFF] = y;
        }
    }
    __syncwarp();

    // ---- store (clips implement the crop) ----
    {
        int M0 = max(MOFF, -off0);
        int M1 = min(MOFF + tlen, N - off0);
        int mA = (M0 + 3) & ~3;
        int mB = M1 & ~3;
        if (lane < mA - M0) { int m = M0 + lane; outr[off0 + m] = ws[m]; }
        if (lane < M1 - mB) { int m = mB + lane; outr[off0 + m] = ws[m]; }
        float4* dst4 = (float4*)(outr + off0);
        #pragma unroll 4
        for (int mi = (mA >> 2) + lane; mi < (mB >> 2); mi += 32)
            dst4[mi] = ws4[mi];
    }
}

__global__ __launch_bounds__(THREADS, 4)
void filtfilt_kernel(const float* __restrict__ x,
                     const float* __restrict__ bc,
                     const float* __restrict__ ac,
                     float* __restrict__ out) {
    __shared__ float sm[WARPS * WWIN];            // 36.75 KB

    const int lane = threadIdx.x & 31;
    const int wid  = threadIdx.x >> 5;
    const int row  = blockIdx.x;

    const float* xr   = x   + (size_t)row * N;
    float*       outr = out + (size_t)row * N;

    const C c = make_coef(bc, ac);

    float*  ws  = sm + wid * WWIN;                // warp-private window
    float4* ws4 = (float4*)ws;

    for (int q = 0; q < SPW; ++q) {
        const int seg  = q * WARPS + wid;
        const int base = seg * SEG;
        if (base >= NE) continue;                 // dead slot
        const int off0 = base - 32;               // mult of 4
        const bool fast = (seg >= 1) && (off0 + WWIN <= N);   // segs 1..13

        if (fast) {                               // LDGSTS bulk load
            const float4* __restrict__ src = (const float4*)(xr + off0);
            #pragma unroll
            for (int i = 0; i < 18; ++i)
                __pipeline_memcpy_async(&ws4[lane + 32 * i],
                                        &src[lane + 32 * i], 16);
            if (lane < 12)
                __pipeline_memcpy_async(&ws4[lane + 576], &src[lane + 576], 16);
            __pipeline_commit();
            __pipeline_wait_prior(0);
        } else {
            fill_direct(ws, xr, off0, lane);      // mirrors
        }
        __syncwarp();

        if (fast) compute_fast(ws, lane, c, outr, off0);
        else      compute_generic(ws, lane, c, outr, base, off0);
        __syncwarp();                             // buffer reuse safety
    }
}

extern "C" void kernel_launch(void* const* d_in, const int* in_sizes, int n_in,
                              void* d_out, int out_size) {
    const float* x = (const float*)d_in[0];
    const float* b = (const float*)d_in[1];
    const float* a = (const float*)d_in[2];
    float* out = (float*)d_out;

    filtfilt_kernel<<<ROWS, THREADS>>>(x, b, a, out);
}